// round 4
// baseline (speedup 1.0000x reference)
#include <cuda_runtime.h>

#define NBINS 36
#define PS 32
#define WARPS_PER_BLOCK 8
#define THREADS (WARPS_PER_BLOCK * 32)

#define TWO_PI_F 6.283185307179586f
#define PI_F     3.14159265358979f

__global__ __launch_bounds__(THREADS, 7)
void orient_kernel(const float* __restrict__ x,
                   const float* __restrict__ gxw,
                   const float* __restrict__ gyw,
                   const float* __restrict__ smw,
                   const float* __restrict__ gk,
                   float* __restrict__ out,
                   int B)
{
    __shared__ float shist[WARPS_PER_BLOCK][NBINS];

    const int warp = threadIdx.x >> 5;
    const int lane = threadIdx.x & 31;
    const int patch = blockIdx.x * WARPS_PER_BLOCK + warp;
    if (patch >= B) return;

    shist[warp][lane] = 0.0f;
    if (lane < NBINS - 32) shist[warp][32 + lane] = 0.0f;
    __syncwarp();

    const float wx0 = __ldg(gxw + 0), wx1 = __ldg(gxw + 1), wx2 = __ldg(gxw + 2);
    const float wy0 = __ldg(gyw + 0), wy1 = __ldg(gyw + 1), wy2 = __ldg(gyw + 2);

    const float* p  = x + (size_t)patch * (PS * PS) + lane;
    const float* gp = gk + lane;

    // rolling 3-row window; prefetch distance 1 row (~50 issue slots of slack)
    float vcur  = __ldg(p);            // row 0
    float vprev = vcur;                // row -1 (replicate)
    float vnext = __ldg(p + PS);       // row 1

#pragma unroll
    for (int r = 0; r < PS; ++r) {
        const float b    = vcur;
        const float a_up = vprev;
        const float c_dn = vnext;

        // prefetch row r+2 (clamped) for next iteration
        const int rn = (r + 2 > PS - 1) ? (PS - 1) : (r + 2);
        vprev = vcur;
        vcur  = vnext;
        vnext = __ldg(p + rn * PS);

        // shfl up/down clamp at warp edges -> returns own value = replicate pad
        const float left  = __shfl_up_sync(0xffffffffu, b, 1);
        const float right = __shfl_down_sync(0xffffffffu, b, 1);

        const float gx = wx0 * left + wx1 * b    + wx2 * right;
        const float gy = wy0 * a_up + wy1 * b    + wy2 * c_dn;

        const float g = __ldg(gp + r * PS);
        const float mag = sqrtf(gx * gx + gy * gy + 1e-10f) * g;

        if (mag > 0.001f) {
            const float ori = atan2f(gy, gx);                  // libdevice-exact, frozen
            const float m = (ori < 0.0f) ? (ori + TWO_PI_F) : ori;
            const float ob = (36.0f * m) / TWO_PI_F;           // IEEE divide, frozen
            const float f = floorf(ob);
            const float wo1 = ob - f;
            int bin = (int)f;
            if (bin >= NBINS) bin -= NBINS;
            atomicAdd(&shist[warp][bin], (1.0f - wo1) * mag);
        }
    }
    __syncwarp();

    // smoothing (conv3, zero pad) + argmax over 36 bins, in-warp
    const float s0 = __ldg(smw + 0), s1 = __ldg(smw + 1), s2 = __ldg(smw + 2);
    const float inv = 1.0f / (float)(PS * PS);

    float bestv;
    int besti;
    {
        const int i = lane;                         // bins 0..31
        const float hm = (i > 0) ? shist[warp][i - 1] * inv : 0.0f;
        const float hc = shist[warp][i] * inv;
        const float hp = shist[warp][i + 1] * inv;  // i+1 <= 32 < 36, valid
        bestv = s0 * hm + s1 * hc + s2 * hp;
        besti = i;
    }
    if (lane < NBINS - 32) {                        // bins 32..35
        const int i = lane + 32;
        const float hm = shist[warp][i - 1] * inv;
        const float hc = shist[warp][i] * inv;
        const float hp = (i + 1 < NBINS) ? shist[warp][i + 1] * inv : 0.0f;
        const float sm = s0 * hm + s1 * hc + s2 * hp;
        if (sm > bestv) { bestv = sm; besti = i; }  // strict >: lower index wins ties
    }
#pragma unroll
    for (int off = 16; off > 0; off >>= 1) {
        const float ov = __shfl_down_sync(0xffffffffu, bestv, off);
        const int   oi = __shfl_down_sync(0xffffffffu, besti, off);
        if (ov > bestv || (ov == bestv && oi < besti)) { bestv = ov; besti = oi; }
    }

    if (lane == 0) {
        out[patch] = -((TWO_PI_F * (float)besti) / 36.0f - PI_F);
    }
}

extern "C" void kernel_launch(void* const* d_in, const int* in_sizes, int n_in,
                              void* d_out, int out_size)
{
    const float* x   = (const float*)d_in[0];
    const float* gxw = (const float*)d_in[1];
    const float* gyw = (const float*)d_in[2];
    const float* smw = (const float*)d_in[3];
    const float* gk  = (const float*)d_in[4];
    float* out = (float*)d_out;

    const int B = out_size;
    const int grid = (B + WARPS_PER_BLOCK - 1) / WARPS_PER_BLOCK;
    orient_kernel<<<grid, THREADS>>>(x, gxw, gyw, smw, gk, out, B);
}

// round 5
// speedup vs baseline: 1.0603x; 1.0603x over previous
#include <cuda_runtime.h>

#define NBINS 36
#define PS 32
#define WARPS_PER_BLOCK 8
#define THREADS (WARPS_PER_BLOCK * 32)
#define CHUNK 8

#define TWO_PI_F 6.283185307179586f
#define PI_F     3.14159265358979f

__global__ __launch_bounds__(THREADS, 6)
void orient_kernel(const float* __restrict__ x,
                   const float* __restrict__ gxw,
                   const float* __restrict__ gyw,
                   const float* __restrict__ smw,
                   const float* __restrict__ gk,
                   float* __restrict__ out,
                   int B)
{
    __shared__ float shist[WARPS_PER_BLOCK][NBINS];
    __shared__ float sgk[PS * PS];

    // cooperative gk load (4KB, once per block), before any early exit
    for (int i = threadIdx.x; i < PS * PS; i += THREADS)
        sgk[i] = __ldg(gk + i);
    __syncthreads();

    const int warp = threadIdx.x >> 5;
    const int lane = threadIdx.x & 31;
    const int patch = blockIdx.x * WARPS_PER_BLOCK + warp;
    if (patch >= B) return;

    shist[warp][lane] = 0.0f;
    if (lane < NBINS - 32) shist[warp][32 + lane] = 0.0f;
    __syncwarp();

    const float wx0 = __ldg(gxw + 0), wx1 = __ldg(gxw + 1), wx2 = __ldg(gxw + 2);
    const float wy0 = __ldg(gyw + 0), wy1 = __ldg(gyw + 1), wy2 = __ldg(gyw + 2);

    const float* p = x + (size_t)patch * (PS * PS) + lane;

    // process rows in chunks of CHUNK; v window holds rows [c0-1 .. c0+CHUNK] (clamped)
#pragma unroll
    for (int c0 = 0; c0 < PS; c0 += CHUNK) {
        float v[CHUNK + 2];
#pragma unroll
        for (int i = 0; i < CHUNK + 2; ++i) {
            int r = c0 - 1 + i;
            r = (r < 0) ? 0 : ((r > PS - 1) ? PS - 1 : r);
            v[i] = __ldg(p + r * PS);
        }

#pragma unroll
        for (int i = 0; i < CHUNK; ++i) {
            const int r = c0 + i;
            // gk row 0 is identically zero -> every pixel masked -> zero
            // histogram contribution; skipping is bit-exact.
            if (r == 0) continue;

            const float b    = v[i + 1];
            const float a_up = v[i];       // row r-1 (replicate-clamped)
            const float c_dn = v[i + 2];   // row r+1 (replicate-clamped)

            // shfl up/down clamp at warp edges -> returns own value = replicate pad
            const float left  = __shfl_up_sync(0xffffffffu, b, 1);
            const float right = __shfl_down_sync(0xffffffffu, b, 1);

            const float gx = wx0 * left + wx1 * b    + wx2 * right;
            const float gy = wy0 * a_up + wy1 * b    + wy2 * c_dn;

            const float g = sgk[r * PS + lane];
            const float mag = sqrtf(gx * gx + gy * gy + 1e-10f) * g;

            if (mag > 0.001f) {
                const float ori = atan2f(gy, gx);                  // libdevice-exact, frozen
                const float m = (ori < 0.0f) ? (ori + TWO_PI_F) : ori;
                const float ob = (36.0f * m) / TWO_PI_F;           // IEEE divide, frozen
                const float f = floorf(ob);
                const float wo1 = ob - f;
                int bin = (int)f;
                if (bin >= NBINS) bin -= NBINS;
                atomicAdd(&shist[warp][bin], (1.0f - wo1) * mag);
            }
        }
    }
    __syncwarp();

    // smoothing (conv3, zero pad) + argmax over 36 bins, in-warp
    const float s0 = __ldg(smw + 0), s1 = __ldg(smw + 1), s2 = __ldg(smw + 2);
    const float inv = 1.0f / (float)(PS * PS);

    float bestv;
    int besti;
    {
        const int i = lane;                         // bins 0..31
        const float hm = (i > 0) ? shist[warp][i - 1] * inv : 0.0f;
        const float hc = shist[warp][i] * inv;
        const float hp = shist[warp][i + 1] * inv;  // i+1 <= 32 < 36, valid
        bestv = s0 * hm + s1 * hc + s2 * hp;
        besti = i;
    }
    if (lane < NBINS - 32) {                        // bins 32..35
        const int i = lane + 32;
        const float hm = shist[warp][i - 1] * inv;
        const float hc = shist[warp][i] * inv;
        const float hp = (i + 1 < NBINS) ? shist[warp][i + 1] * inv : 0.0f;
        const float sm = s0 * hm + s1 * hc + s2 * hp;
        if (sm > bestv) { bestv = sm; besti = i; }  // strict >: lower index wins ties
    }
#pragma unroll
    for (int off = 16; off > 0; off >>= 1) {
        const float ov = __shfl_down_sync(0xffffffffu, bestv, off);
        const int   oi = __shfl_down_sync(0xffffffffu, besti, off);
        if (ov > bestv || (ov == bestv && oi < besti)) { bestv = ov; besti = oi; }
    }

    if (lane == 0) {
        out[patch] = -((TWO_PI_F * (float)besti) / 36.0f - PI_F);
    }
}

extern "C" void kernel_launch(void* const* d_in, const int* in_sizes, int n_in,
                              void* d_out, int out_size)
{
    const float* x   = (const float*)d_in[0];
    const float* gxw = (const float*)d_in[1];
    const float* gyw = (const float*)d_in[2];
    const float* smw = (const float*)d_in[3];
    const float* gk  = (const float*)d_in[4];
    float* out = (float*)d_out;

    const int B = out_size;
    const int grid = (B + WARPS_PER_BLOCK - 1) / WARPS_PER_BLOCK;
    orient_kernel<<<grid, THREADS>>>(x, gxw, gyw, smw, gk, out, B);
}

// round 6
// speedup vs baseline: 1.0680x; 1.0073x over previous
#include <cuda_runtime.h>

#define NBINS 36
#define PS 32
#define WARPS_PER_BLOCK 8
#define THREADS (WARPS_PER_BLOCK * 32)
#define CHUNK 8

#define TWO_PI_F 6.283185307179586f
#define PI_F     3.14159265358979f

__global__ __launch_bounds__(THREADS, 6)
void orient_kernel(const float* __restrict__ x,
                   const float* __restrict__ gxw,
                   const float* __restrict__ gyw,
                   const float* __restrict__ smw,
                   const float* __restrict__ gk,
                   float* __restrict__ out,
                   int B)
{
    __shared__ float shist[WARPS_PER_BLOCK][NBINS];
    __shared__ float sgk[PS * PS];

    // cooperative gk load (4KB, once per block), before any early exit
    for (int i = threadIdx.x; i < PS * PS; i += THREADS)
        sgk[i] = __ldg(gk + i);
    __syncthreads();

    const int warp = threadIdx.x >> 5;
    const int lane = threadIdx.x & 31;
    const int patch = blockIdx.x * WARPS_PER_BLOCK + warp;
    if (patch >= B) return;

    shist[warp][lane] = 0.0f;
    if (lane < NBINS - 32) shist[warp][32 + lane] = 0.0f;
    __syncwarp();

    const float wx0 = __ldg(gxw + 0), wx1 = __ldg(gxw + 1), wx2 = __ldg(gxw + 2);
    const float wy0 = __ldg(gyw + 0), wy1 = __ldg(gyw + 1), wy2 = __ldg(gyw + 2);

    const float* p = x + (size_t)patch * (PS * PS) + lane;

    // rows in chunks of CHUNK; v window holds rows [c0-1 .. c0+CHUNK] (clamped)
#pragma unroll
    for (int c0 = 0; c0 < PS; c0 += CHUNK) {
        float v[CHUNK + 2];
#pragma unroll
        for (int i = 0; i < CHUNK + 2; ++i) {
            int r = c0 - 1 + i;
            r = (r < 0) ? 0 : ((r > PS - 1) ? PS - 1 : r);
            v[i] = __ldg(p + r * PS);
        }

#pragma unroll
        for (int i = 0; i < CHUNK; ++i) {
            const int r = c0 + i;
            // gk row 0 is identically zero -> all lanes masked -> skip (bit-exact,
            // resolved at compile time inside the unrolled loop)
            if (r == 0) continue;

            const float b    = v[i + 1];
            const float a_up = v[i];       // row r-1 (replicate-clamped)
            const float c_dn = v[i + 2];   // row r+1 (replicate-clamped)

            // shfl up/down clamp at warp edges -> returns own value = replicate pad
            const float left  = __shfl_up_sync(0xffffffffu, b, 1);
            const float right = __shfl_down_sync(0xffffffffu, b, 1);

            const float gx = wx0 * left + wx1 * b    + wx2 * right;
            const float gy = wy0 * a_up + wy1 * b    + wy2 * c_dn;

            const float g = sgk[r * PS + lane];
            const float mag = sqrtf(gx * gx + gy * gy + 1e-10f) * g;

            // ---- branchless: compute the frozen numeric core unconditionally ----
            const float ori = atan2f(gy, gx);                  // libdevice-exact, frozen
            const float m = (ori < 0.0f) ? (ori + TWO_PI_F) : ori;
            const float ob = (36.0f * m) / TWO_PI_F;           // IEEE divide, frozen
            const float f = floorf(ob);
            const float wo1 = ob - f;
            int bin = (int)f;
            if (bin >= NBINS) bin -= NBINS;
            const float w = (1.0f - wo1) * mag;

            // only the atomic is predicated -> same histogram bits, no BSSY walls
            if (mag > 0.001f)
                atomicAdd(&shist[warp][bin], w);
        }
    }
    __syncwarp();

    // smoothing (conv3, zero pad) + argmax over 36 bins, in-warp
    const float s0 = __ldg(smw + 0), s1 = __ldg(smw + 1), s2 = __ldg(smw + 2);
    const float inv = 1.0f / (float)(PS * PS);

    float bestv;
    int besti;
    {
        const int i = lane;                         // bins 0..31
        const float hm = (i > 0) ? shist[warp][i - 1] * inv : 0.0f;
        const float hc = shist[warp][i] * inv;
        const float hp = shist[warp][i + 1] * inv;  // i+1 <= 32 < 36, valid
        bestv = s0 * hm + s1 * hc + s2 * hp;
        besti = i;
    }
    if (lane < NBINS - 32) {                        // bins 32..35
        const int i = lane + 32;
        const float hm = shist[warp][i - 1] * inv;
        const float hc = shist[warp][i] * inv;
        const float hp = (i + 1 < NBINS) ? shist[warp][i + 1] * inv : 0.0f;
        const float sm = s0 * hm + s1 * hc + s2 * hp;
        if (sm > bestv) { bestv = sm; besti = i; }  // strict >: lower index wins ties
    }
#pragma unroll
    for (int off = 16; off > 0; off >>= 1) {
        const float ov = __shfl_down_sync(0xffffffffu, bestv, off);
        const int   oi = __shfl_down_sync(0xffffffffu, besti, off);
        if (ov > bestv || (ov == bestv && oi < besti)) { bestv = ov; besti = oi; }
    }

    if (lane == 0) {
        out[patch] = -((TWO_PI_F * (float)besti) / 36.0f - PI_F);
    }
}

extern "C" void kernel_launch(void* const* d_in, const int* in_sizes, int n_in,
                              void* d_out, int out_size)
{
    const float* x   = (const float*)d_in[0];
    const float* gxw = (const float*)d_in[1];
    const float* gyw = (const float*)d_in[2];
    const float* smw = (const float*)d_in[3];
    const float* gk  = (const float*)d_in[4];
    float* out = (float*)d_out;

    const int B = out_size;
    const int grid = (B + WARPS_PER_BLOCK - 1) / WARPS_PER_BLOCK;
    orient_kernel<<<grid, THREADS>>>(x, gxw, gyw, smw, gk, out, B);
}

// round 7
// speedup vs baseline: 1.1701x; 1.0956x over previous
#include <cuda_runtime.h>

#define NBINS 36
#define PS 32
#define WARPS_PER_BLOCK 8
#define THREADS (WARPS_PER_BLOCK * 32)
#define CHUNK 8

#define TWO_PI_F 6.283185307179586f
#define PI_F     3.14159265358979f

__global__ __launch_bounds__(THREADS, 6)
void orient_kernel(const float* __restrict__ x,
                   const float* __restrict__ gxw,
                   const float* __restrict__ gyw,
                   const float* __restrict__ smw,
                   const float* __restrict__ gk,
                   float* __restrict__ out,
                   int B)
{
    __shared__ float shist[WARPS_PER_BLOCK][NBINS];
    __shared__ float sgk[PS * PS];

    // cooperative gk load (4KB, once per block), before any early exit
    for (int i = threadIdx.x; i < PS * PS; i += THREADS)
        sgk[i] = __ldg(gk + i);
    __syncthreads();

    const int warp = threadIdx.x >> 5;
    const int lane = threadIdx.x & 31;
    const int patch = blockIdx.x * WARPS_PER_BLOCK + warp;
    if (patch >= B) return;

    shist[warp][lane] = 0.0f;
    if (lane < NBINS - 32) shist[warp][32 + lane] = 0.0f;
    __syncwarp();

    const float wx0 = __ldg(gxw + 0), wx1 = __ldg(gxw + 1), wx2 = __ldg(gxw + 2);
    const float wy0 = __ldg(gyw + 0), wy1 = __ldg(gyw + 1), wy2 = __ldg(gyw + 2);

    // RN(1/2pi) as a compile-time constant for the Markstein division
    const float rc = 1.0f / TWO_PI_F;   // constant-folded in RN: 0x3E22F983

    const float* p = x + (size_t)patch * (PS * PS) + lane;

    // rows in chunks of CHUNK; v window holds rows [c0-1 .. c0+CHUNK] (clamped)
#pragma unroll
    for (int c0 = 0; c0 < PS; c0 += CHUNK) {
        float v[CHUNK + 2];
#pragma unroll
        for (int i = 0; i < CHUNK + 2; ++i) {
            int r = c0 - 1 + i;
            r = (r < 0) ? 0 : ((r > PS - 1) ? PS - 1 : r);
            v[i] = __ldg(p + r * PS);
        }

#pragma unroll
        for (int i = 0; i < CHUNK; ++i) {
            const int r = c0 + i;
            // gk row 0 is identically zero -> all lanes masked -> skip (bit-exact,
            // resolved at compile time inside the unrolled loop)
            if (r == 0) continue;

            const float b    = v[i + 1];
            const float a_up = v[i];       // row r-1 (replicate-clamped)
            const float c_dn = v[i + 2];   // row r+1 (replicate-clamped)

            // shfl up/down clamp at warp edges -> returns own value = replicate pad
            const float left  = __shfl_up_sync(0xffffffffu, b, 1);
            const float right = __shfl_down_sync(0xffffffffu, b, 1);

            const float gx = wx0 * left + wx1 * b    + wx2 * right;
            const float gy = wy0 * a_up + wy1 * b    + wy2 * c_dn;

            const float g = sgk[r * PS + lane];
            const float mag = sqrtf(gx * gx + gy * gy + 1e-10f) * g;

            // ---- frozen numeric core (bit-exact vs XLA) ----
            const float ori = atan2f(gy, gx);                  // libdevice-exact
            const float m = (ori < 0.0f) ? (ori + TWO_PI_F) : ori;

            // ob = (36*m) / 2pi via Markstein correctly-rounded constant division:
            // bit-identical to div.rn.f32 for all normal inputs, no MUFU, no slowpath.
            const float a36 = 36.0f * m;
            const float q0  = a36 * rc;
            const float rr  = fmaf(-TWO_PI_F, q0, a36);        // exact residual (FMA)
            const float ob  = fmaf(rr, rc, q0);                // = RN(a36 / 2pi)

            const float f = floorf(ob);
            const float wo1 = ob - f;
            int bin = (int)f;
            if (bin >= NBINS) bin -= NBINS;
            const float w = (1.0f - wo1) * mag;

            // only the atomic is predicated -> same histogram bits
            if (mag > 0.001f)
                atomicAdd(&shist[warp][bin], w);
        }
    }
    __syncwarp();

    // smoothing (conv3, zero pad) + argmax over 36 bins, in-warp
    const float s0 = __ldg(smw + 0), s1 = __ldg(smw + 1), s2 = __ldg(smw + 2);
    const float inv = 1.0f / (float)(PS * PS);

    float bestv;
    int besti;
    {
        const int i = lane;                         // bins 0..31
        const float hm = (i > 0) ? shist[warp][i - 1] * inv : 0.0f;
        const float hc = shist[warp][i] * inv;
        const float hp = shist[warp][i + 1] * inv;  // i+1 <= 32 < 36, valid
        bestv = s0 * hm + s1 * hc + s2 * hp;
        besti = i;
    }
    if (lane < NBINS - 32) {                        // bins 32..35
        const int i = lane + 32;
        const float hm = shist[warp][i - 1] * inv;
        const float hc = shist[warp][i] * inv;
        const float hp = (i + 1 < NBINS) ? shist[warp][i + 1] * inv : 0.0f;
        const float sm = s0 * hm + s1 * hc + s2 * hp;
        if (sm > bestv) { bestv = sm; besti = i; }  // strict >: lower index wins ties
    }
#pragma unroll
    for (int off = 16; off > 0; off >>= 1) {
        const float ov = __shfl_down_sync(0xffffffffu, bestv, off);
        const int   oi = __shfl_down_sync(0xffffffffu, besti, off);
        if (ov > bestv || (ov == bestv && oi < besti)) { bestv = ov; besti = oi; }
    }

    if (lane == 0) {
        out[patch] = -((TWO_PI_F * (float)besti) / 36.0f - PI_F);
    }
}

extern "C" void kernel_launch(void* const* d_in, const int* in_sizes, int n_in,
                              void* d_out, int out_size)
{
    const float* x   = (const float*)d_in[0];
    const float* gxw = (const float*)d_in[1];
    const float* gyw = (const float*)d_in[2];
    const float* smw = (const float*)d_in[3];
    const float* gk  = (const float*)d_in[4];
    float* out = (float*)d_out;

    const int B = out_size;
    const int grid = (B + WARPS_PER_BLOCK - 1) / WARPS_PER_BLOCK;
    orient_kernel<<<grid, THREADS>>>(x, gxw, gyw, smw, gk, out, B);
}

// round 8
// speedup vs baseline: 1.2424x; 1.0618x over previous
#include <cuda_runtime.h>

#define NBINS 36
#define PS 32
#define WARPS_PER_BLOCK 8
#define THREADS (WARPS_PER_BLOCK * 32)
#define PATCHES_PER_BLOCK (WARPS_PER_BLOCK * 2)
#define CHUNK 4

#define TWO_PI_F 6.283185307179586f
#define PI_F     3.14159265358979f

__global__ __launch_bounds__(THREADS, 5)
void orient_kernel(const float* __restrict__ x,
                   const float* __restrict__ gxw,
                   const float* __restrict__ gyw,
                   const float* __restrict__ smw,
                   const float* __restrict__ gk,
                   float* __restrict__ out,
                   int B)
{
    __shared__ float shist[PATCHES_PER_BLOCK][NBINS];
    __shared__ float sgk[PS * PS];

    for (int i = threadIdx.x; i < PS * PS; i += THREADS)
        sgk[i] = __ldg(gk + i);
    __syncthreads();

    const int warp = threadIdx.x >> 5;
    const int lane = threadIdx.x & 31;
    const int half = lane >> 4;          // which patch within the warp
    const int k    = lane & 15;          // column-pair index (cols 2k, 2k+1)
    const int hrow = warp * 2 + half;

    int patch = blockIdx.x * PATCHES_PER_BLOCK + hrow;
    const bool valid = (patch < B);
    if (!valid) patch = B - 1;           // clamp addressing; own hist row, no out write

    float* hist = shist[hrow];
    hist[k] = 0.0f;
    hist[k + 16] = 0.0f;
    if (k < 4) hist[k + 32] = 0.0f;
    __syncwarp();

    const float wx0 = __ldg(gxw + 0), wx1 = __ldg(gxw + 1), wx2 = __ldg(gxw + 2);
    const float wy0 = __ldg(gyw + 0), wy1 = __ldg(gyw + 1), wy2 = __ldg(gyw + 2);
    const float rc = 1.0f / TWO_PI_F;    // RN(1/2pi), constant-folded

    const float2* p   = reinterpret_cast<const float2*>(x + (size_t)patch * (PS * PS)) + k;
    const float2* gk2 = reinterpret_cast<const float2*>(sgk) + k;

#pragma unroll 1
    for (int c0 = 0; c0 < PS; c0 += CHUNK) {
        float2 v[CHUNK + 2];
#pragma unroll
        for (int i = 0; i < CHUNK + 2; ++i) {
            int r = c0 - 1 + i;
            r = (r < 0) ? 0 : ((r > PS - 1) ? PS - 1 : r);
            v[i] = __ldg(p + r * (PS / 2));
        }

#pragma unroll
        for (int i = 0; i < CHUNK; ++i) {
            const int r = c0 + i;
            // gk row 0 is identically zero -> all pixels masked -> skip (bit-exact)
            if (r == 0) continue;

            const float2 b  = v[i + 1];
            const float2 up = v[i];
            const float2 dn = v[i + 2];

            float left_in  = __shfl_up_sync(0xffffffffu, b.y, 1);   // col 2k-1
            float right_in = __shfl_down_sync(0xffffffffu, b.x, 1); // col 2k+2
            if (k == 0)  left_in  = b.x;   // replicate pad (also kills cross-half leak)
            if (k == 15) right_in = b.y;

            const float2 g2 = gk2[r * (PS / 2)];

            // ---------------- pixel 0: column 2k ----------------
            {
                const float gx = wx0 * left_in + wx1 * b.x + wx2 * b.y;
                const float gy = wy0 * up.x    + wy1 * b.x + wy2 * dn.x;
                const float S = gx * gx + gy * gy + 1e-10f;
                float rs; asm("rsqrt.approx.f32 %0, %1;" : "=f"(rs) : "f"(S));
                const float mag = (S * rs) * g2.x;          // ~2.5e-7 rel approx of sqrt(S)*g
                const float ori = atan2f(gy, gx);           // libdevice-exact, frozen
                const float m = (ori < 0.0f) ? (ori + TWO_PI_F) : ori;
                const float a36 = 36.0f * m;                // Markstein correctly-rounded /2pi
                const float q0  = a36 * rc;
                const float rr  = fmaf(-TWO_PI_F, q0, a36);
                const float ob  = fmaf(rr, rc, q0);
                const float f = floorf(ob);
                const float wo1 = ob - f;
                int bin = (int)f;
                if (bin >= NBINS) bin -= NBINS;
                const float w = (1.0f - wo1) * mag;
                if (mag > 0.001f) atomicAdd(&hist[bin], w);
            }
            // ---------------- pixel 1: column 2k+1 ----------------
            {
                const float gx = wx0 * b.x + wx1 * b.y + wx2 * right_in;
                const float gy = wy0 * up.y + wy1 * b.y + wy2 * dn.y;
                const float S = gx * gx + gy * gy + 1e-10f;
                float rs; asm("rsqrt.approx.f32 %0, %1;" : "=f"(rs) : "f"(S));
                const float mag = (S * rs) * g2.y;
                const float ori = atan2f(gy, gx);
                const float m = (ori < 0.0f) ? (ori + TWO_PI_F) : ori;
                const float a36 = 36.0f * m;
                const float q0  = a36 * rc;
                const float rr  = fmaf(-TWO_PI_F, q0, a36);
                const float ob  = fmaf(rr, rc, q0);
                const float f = floorf(ob);
                const float wo1 = ob - f;
                int bin = (int)f;
                if (bin >= NBINS) bin -= NBINS;
                const float w = (1.0f - wo1) * mag;
                if (mag > 0.001f) atomicAdd(&hist[bin], w);
            }
        }
    }
    __syncwarp();

    // smoothing (conv3, zero pad) + argmax over 36 bins, per half-warp (width 16)
    const float s0 = __ldg(smw + 0), s1 = __ldg(smw + 1), s2 = __ldg(smw + 2);
    const float inv = 1.0f / (float)(PS * PS);

    float bestv;
    int besti;
    {
        const int i = k;                              // bins 0..15
        const float hm = (i > 0) ? hist[i - 1] * inv : 0.0f;
        const float hc = hist[i] * inv;
        const float hp = hist[i + 1] * inv;
        bestv = s0 * hm + s1 * hc + s2 * hp;
        besti = i;
    }
    {
        const int i = k + 16;                         // bins 16..31 (i+1 <= 32, valid)
        const float hm = hist[i - 1] * inv;
        const float hc = hist[i] * inv;
        const float hp = hist[i + 1] * inv;
        const float sm = s0 * hm + s1 * hc + s2 * hp;
        if (sm > bestv) { bestv = sm; besti = i; }    // strict >: lower index wins
    }
    if (k < 4) {                                      // bins 32..35
        const int i = k + 32;
        const float hm = hist[i - 1] * inv;
        const float hc = hist[i] * inv;
        const float hp = (i + 1 < NBINS) ? hist[i + 1] * inv : 0.0f;
        const float sm = s0 * hm + s1 * hc + s2 * hp;
        if (sm > bestv) { bestv = sm; besti = i; }
    }
#pragma unroll
    for (int off = 8; off > 0; off >>= 1) {
        const float ov = __shfl_down_sync(0xffffffffu, bestv, off, 16);
        const int   oi = __shfl_down_sync(0xffffffffu, besti, off, 16);
        if (ov > bestv || (ov == bestv && oi < besti)) { bestv = ov; besti = oi; }
    }

    if (k == 0 && valid) {
        out[patch] = -((TWO_PI_F * (float)besti) / 36.0f - PI_F);
    }
}

extern "C" void kernel_launch(void* const* d_in, const int* in_sizes, int n_in,
                              void* d_out, int out_size)
{
    const float* x   = (const float*)d_in[0];
    const float* gxw = (const float*)d_in[1];
    const float* gyw = (const float*)d_in[2];
    const float* smw = (const float*)d_in[3];
    const float* gk  = (const float*)d_in[4];
    float* out = (float*)d_out;

    const int B = out_size;
    const int grid = (B + PATCHES_PER_BLOCK - 1) / PATCHES_PER_BLOCK;
    orient_kernel<<<grid, THREADS>>>(x, gxw, gyw, smw, gk, out, B);
}

// round 9
// speedup vs baseline: 1.3137x; 1.0574x over previous
#include <cuda_runtime.h>

#define NBINS 36
#define PS 32
#define WARPS_PER_BLOCK 8
#define THREADS (WARPS_PER_BLOCK * 32)
#define PATCHES_PER_BLOCK (WARPS_PER_BLOCK * 2)
#define CHUNK 4

#define TWO_PI_F 6.283185307179586f
#define PI_F     3.14159265358979f

__global__ __launch_bounds__(THREADS, 6)
void orient_kernel(const float* __restrict__ x,
                   const float* __restrict__ gxw,
                   const float* __restrict__ gyw,
                   const float* __restrict__ smw,
                   const float* __restrict__ gk,
                   float* __restrict__ out,
                   int B)
{
    __shared__ float shist[PATCHES_PER_BLOCK][NBINS];
    __shared__ float sgk[PS * PS];

    for (int i = threadIdx.x; i < PS * PS; i += THREADS)
        sgk[i] = __ldg(gk + i);
    __syncthreads();

    const int warp = threadIdx.x >> 5;
    const int lane = threadIdx.x & 31;
    const int half = lane >> 4;          // which patch within the warp
    const int k    = lane & 15;          // column-pair index (cols 2k, 2k+1)
    const int hrow = warp * 2 + half;

    int patch = blockIdx.x * PATCHES_PER_BLOCK + hrow;
    const bool valid = (patch < B);
    if (!valid) patch = B - 1;           // clamp addressing; own hist row, no out write

    float* hist = shist[hrow];
    hist[k] = 0.0f;
    hist[k + 16] = 0.0f;
    if (k < 4) hist[k + 32] = 0.0f;
    __syncwarp();

    const float wx0 = __ldg(gxw + 0), wx1 = __ldg(gxw + 1), wx2 = __ldg(gxw + 2);
    const float wy0 = __ldg(gyw + 0), wy1 = __ldg(gyw + 1), wy2 = __ldg(gyw + 2);
    const float rc = 1.0f / TWO_PI_F;    // RN(1/2pi), constant-folded

    const float2* p   = reinterpret_cast<const float2*>(x + (size_t)patch * (PS * PS)) + k;
    const float2* gk2 = reinterpret_cast<const float2*>(sgk) + k;

    // sliding window v[0..5] = rows c0-1 .. c0+4 (clamped); carry 2 rows across chunks
    float2 v[CHUNK + 2];
    {   // prologue for c0 = 0: rows -1(=0),0,1,2,3,4
        v[1] = __ldg(p + 0 * (PS / 2));
        v[0] = v[1];
        v[2] = __ldg(p + 1 * (PS / 2));
        v[3] = __ldg(p + 2 * (PS / 2));
        v[4] = __ldg(p + 3 * (PS / 2));
        v[5] = __ldg(p + 4 * (PS / 2));
    }

#pragma unroll 1
    for (int c0 = 0; c0 < PS; c0 += CHUNK) {
        if (c0 > 0) {
            // rotate carry: old rows c0-1, c0 come from previous window's v[4], v[5]
            v[0] = v[4];
            v[1] = v[5];
#pragma unroll
            for (int i = 0; i < CHUNK; ++i) {
                int r = c0 + 1 + i;                       // rows c0+1 .. c0+4
                r = (r > PS - 1) ? PS - 1 : r;
                v[2 + i] = __ldg(p + r * (PS / 2));
            }
        }

#pragma unroll
        for (int i = 0; i < CHUNK; ++i) {
            const int r = c0 + i;
            // gk row 0 is identically zero -> all pixels masked -> skip (bit-exact)
            if (r == 0) continue;

            const float2 b  = v[i + 1];
            const float2 up = v[i];
            const float2 dn = v[i + 2];

            float left_in  = __shfl_up_sync(0xffffffffu, b.y, 1);   // col 2k-1
            float right_in = __shfl_down_sync(0xffffffffu, b.x, 1); // col 2k+2
            if (k == 0)  left_in  = b.x;   // replicate pad (also kills cross-half leak)
            if (k == 15) right_in = b.y;

            const float2 g2 = gk2[r * (PS / 2)];

            // ---------------- pixel 0: column 2k ----------------
            {
                const float gx = wx0 * left_in + wx1 * b.x + wx2 * b.y;
                const float gy = wy0 * up.x    + wy1 * b.x + wy2 * dn.x;
                const float S = gx * gx + gy * gy + 1e-10f;
                float rs; asm("rsqrt.approx.f32 %0, %1;" : "=f"(rs) : "f"(S));
                const float mag = (S * rs) * g2.x;
                const float ori = atan2f(gy, gx);           // libdevice-exact, frozen
                const float m = (ori < 0.0f) ? (ori + TWO_PI_F) : ori;
                const float a36 = 36.0f * m;                // Markstein RN /2pi, frozen
                const float q0  = a36 * rc;
                const float rr  = fmaf(-TWO_PI_F, q0, a36);
                const float ob  = fmaf(rr, rc, q0);
                const float f = floorf(ob);
                const float wo1 = ob - f;
                int bin = (int)f;
                if (bin >= NBINS) bin -= NBINS;
                const float w = (1.0f - wo1) * mag;
                if (mag > 0.001f) atomicAdd(&hist[bin], w);
            }
            // ---------------- pixel 1: column 2k+1 ----------------
            {
                const float gx = wx0 * b.x + wx1 * b.y + wx2 * right_in;
                const float gy = wy0 * up.y + wy1 * b.y + wy2 * dn.y;
                const float S = gx * gx + gy * gy + 1e-10f;
                float rs; asm("rsqrt.approx.f32 %0, %1;" : "=f"(rs) : "f"(S));
                const float mag = (S * rs) * g2.y;
                const float ori = atan2f(gy, gx);
                const float m = (ori < 0.0f) ? (ori + TWO_PI_F) : ori;
                const float a36 = 36.0f * m;
                const float q0  = a36 * rc;
                const float rr  = fmaf(-TWO_PI_F, q0, a36);
                const float ob  = fmaf(rr, rc, q0);
                const float f = floorf(ob);
                const float wo1 = ob - f;
                int bin = (int)f;
                if (bin >= NBINS) bin -= NBINS;
                const float w = (1.0f - wo1) * mag;
                if (mag > 0.001f) atomicAdd(&hist[bin], w);
            }
        }
    }
    __syncwarp();

    // smoothing (conv3, zero pad) + argmax over 36 bins, per half-warp (width 16)
    const float s0 = __ldg(smw + 0), s1 = __ldg(smw + 1), s2 = __ldg(smw + 2);
    const float inv = 1.0f / (float)(PS * PS);

    float bestv;
    int besti;
    {
        const int i = k;                              // bins 0..15
        const float hm = (i > 0) ? hist[i - 1] * inv : 0.0f;
        const float hc = hist[i] * inv;
        const float hp = hist[i + 1] * inv;
        bestv = s0 * hm + s1 * hc + s2 * hp;
        besti = i;
    }
    {
        const int i = k + 16;                         // bins 16..31
        const float hm = hist[i - 1] * inv;
        const float hc = hist[i] * inv;
        const float hp = hist[i + 1] * inv;
        const float sm = s0 * hm + s1 * hc + s2 * hp;
        if (sm > bestv) { bestv = sm; besti = i; }    // strict >: lower index wins
    }
    if (k < 4) {                                      // bins 32..35
        const int i = k + 32;
        const float hm = hist[i - 1] * inv;
        const float hc = hist[i] * inv;
        const float hp = (i + 1 < NBINS) ? hist[i + 1] * inv : 0.0f;
        const float sm = s0 * hm + s1 * hc + s2 * hp;
        if (sm > bestv) { bestv = sm; besti = i; }
    }
#pragma unroll
    for (int off = 8; off > 0; off >>= 1) {
        const float ov = __shfl_down_sync(0xffffffffu, bestv, off, 16);
        const int   oi = __shfl_down_sync(0xffffffffu, besti, off, 16);
        if (ov > bestv || (ov == bestv && oi < besti)) { bestv = ov; besti = oi; }
    }

    if (k == 0 && valid) {
        out[patch] = -((TWO_PI_F * (float)besti) / 36.0f - PI_F);
    }
}

extern "C" void kernel_launch(void* const* d_in, const int* in_sizes, int n_in,
                              void* d_out, int out_size)
{
    const float* x   = (const float*)d_in[0];
    const float* gxw = (const float*)d_in[1];
    const float* gyw = (const float*)d_in[2];
    const float* smw = (const float*)d_in[3];
    const float* gk  = (const float*)d_in[4];
    float* out = (float*)d_out;

    const int B = out_size;
    const int grid = (B + PATCHES_PER_BLOCK - 1) / PATCHES_PER_BLOCK;
    orient_kernel<<<grid, THREADS>>>(x, gxw, gyw, smw, gk, out, B);
}